// round 1
// baseline (speedup 1.0000x reference)
#include <cuda_runtime.h>
#include <cuda_bf16.h>
#include <math.h>

// ---------------- problem constants ----------------
#define T_LEN 256
#define HID   2048
#define NHEAD 16
#define DHEAD 128
#define KD    2048     // NHEAD*DHEAD

// ---------------- scratch (device globals; allocation-free) ----------------
__device__ float g_Q0[T_LEN * KD];     // x @ Wq (pre-conv)
__device__ float g_K0[T_LEN * KD];     // x @ Wk (pre-conv)
__device__ float g_V0[T_LEN * KD];     // x @ Wv  (= v)
__device__ float g_qn[T_LEN * KD];     // conv+silu+l2norm q
__device__ float g_kn[T_LEN * KD];     // conv+silu+l2norm k
__device__ float g_beta[T_LEN * NHEAD];
__device__ float g_decay[T_LEN * NHEAD];
__device__ float g_lamb[KD];
__device__ float g_on[T_LEN * KD];     // rmsnorm'd attention output
__device__ float g_hkk[(size_t)T_LEN * NHEAD * DHEAD * DHEAD];  // 256 MB
__device__ float g_hkv[(size_t)T_LEN * NHEAD * DHEAD * DHEAD];  // 256 MB

// ---------------- fp32 SIMT GEMM: C[256,N] = X[256,2048] @ W[2048,N] ----------------
// BM=64, BN=64, BK=16, 256 threads, 4x4 micro-tile.
__global__ void gemm_kernel(const float* __restrict__ X,
                            const float* __restrict__ W,
                            float* __restrict__ C, int N) {
    __shared__ __align__(16) float As[16][64];
    __shared__ __align__(16) float Bs[16][64];
    const int tid = threadIdx.x;
    const int m0 = blockIdx.y * 64;
    const int n0 = blockIdx.x * 64;
    const int tn = tid & 15;       // 0..15 -> n groups of 4
    const int tm = tid >> 4;       // 0..15 -> m groups of 4
    const int lrow = tid >> 2;     // 0..63  (A-tile load row)
    const int lk4  = (tid & 3) * 4;
    const int wrow = tid >> 4;     // 0..15  (B-tile load row)
    const int wn4  = (tid & 15) * 4;

    float acc[4][4];
#pragma unroll
    for (int i = 0; i < 4; i++)
#pragma unroll
        for (int j = 0; j < 4; j++) acc[i][j] = 0.f;

    for (int k0 = 0; k0 < HID; k0 += 16) {
        float4 av = *(const float4*)&X[(m0 + lrow) * HID + k0 + lk4];
        As[lk4 + 0][lrow] = av.x;
        As[lk4 + 1][lrow] = av.y;
        As[lk4 + 2][lrow] = av.z;
        As[lk4 + 3][lrow] = av.w;
        *(float4*)&Bs[wrow][wn4] = *(const float4*)&W[(k0 + wrow) * N + n0 + wn4];
        __syncthreads();
#pragma unroll
        for (int kk = 0; kk < 16; kk++) {
            float4 a4 = *(const float4*)&As[kk][tm * 4];
            float4 b4 = *(const float4*)&Bs[kk][tn * 4];
            float a[4] = {a4.x, a4.y, a4.z, a4.w};
            float b[4] = {b4.x, b4.y, b4.z, b4.w};
#pragma unroll
            for (int i = 0; i < 4; i++)
#pragma unroll
                for (int j = 0; j < 4; j++) acc[i][j] += a[i] * b[j];
        }
        __syncthreads();
    }
#pragma unroll
    for (int i = 0; i < 4; i++) {
        float4 o = make_float4(acc[i][0], acc[i][1], acc[i][2], acc[i][3]);
        *(float4*)&C[(m0 + tm * 4 + i) * N + n0 + tn * 4] = o;
    }
}

// ---------------- beta / decay:  sigmoid(x@Wa+ba), sigmoid(x@Wb+bb) ----------------
// decay = exp(log_sigmoid(z)) = sigmoid(z) exactly.
__global__ void bg_kernel(const float* __restrict__ x,
                          const float* __restrict__ Wa, const float* __restrict__ ba,
                          const float* __restrict__ Wb, const float* __restrict__ bb) {
    const int t = blockIdx.x;
    __shared__ __align__(16) float xs[HID];
    __shared__ float red[4][32];
    const int tid = threadIdx.x;  // 128
    for (int i = tid; i < HID / 4; i += 128)
        *(float4*)&xs[i * 4] = *(const float4*)&x[t * HID + i * 4];
    __syncthreads();
    const int w = tid >> 5, lane = tid & 31;
    const float* Wsel = (lane < 16) ? Wa : Wb;
    const int col = lane & 15;
    float acc = 0.f;
    const int cbeg = w * 512;
#pragma unroll 4
    for (int c = cbeg; c < cbeg + 512; c++)
        acc += xs[c] * Wsel[c * NHEAD + col];
    red[w][lane] = acc;
    __syncthreads();
    if (w == 0) {
        float v = red[0][lane] + red[1][lane] + red[2][lane] + red[3][lane];
        if (lane < 16) {
            float z = v + ba[col];
            g_decay[t * NHEAD + col] = 1.f / (1.f + expf(-z));
        } else {
            float z = v + bb[col];
            g_beta[t * NHEAD + col] = 1.f / (1.f + expf(-z));
        }
    }
}

// ---------------- lambda = softplus(lp) + 0.25 ----------------
__global__ void lamb_kernel(const float* __restrict__ lp) {
    int i = blockIdx.x * 256 + threadIdx.x;
    if (i < KD) {
        float v = lp[i];
        float sp = (v > 20.f) ? v : log1pf(expf(v));
        g_lamb[i] = sp + 0.25f;
    }
}

// ---------------- conv(4)+silu+l2norm for q and k ----------------
__device__ __forceinline__ void conv_silu_l2(const float* __restrict__ src,
                                             const float* __restrict__ cw,
                                             float* __restrict__ dst,
                                             int t, int tid) {
    const int c0 = tid * 8;
    float wv[8][4];
#pragma unroll
    for (int e = 0; e < 8; e++) {
        float4 f = *(const float4*)&cw[(c0 + e) * 4];
        wv[e][0] = f.x; wv[e][1] = f.y; wv[e][2] = f.z; wv[e][3] = f.w;
    }
    float y[8];
#pragma unroll
    for (int e = 0; e < 8; e++) y[e] = 0.f;
#pragma unroll
    for (int i = 0; i < 4; i++) {
        int ts = t + i - 3;
        if (ts >= 0) {
            float4 xa = *(const float4*)&src[ts * HID + c0];
            float4 xb = *(const float4*)&src[ts * HID + c0 + 4];
            float xv[8] = {xa.x, xa.y, xa.z, xa.w, xb.x, xb.y, xb.z, xb.w};
#pragma unroll
            for (int e = 0; e < 8; e++) y[e] += xv[e] * wv[e][i];
        }
    }
#pragma unroll
    for (int e = 0; e < 8; e++) {
        float s = 1.f / (1.f + expf(-y[e]));
        y[e] *= s;
    }
    float ss = 0.f;
#pragma unroll
    for (int e = 0; e < 8; e++) ss += y[e] * y[e];
    // reduce across the 16 threads of this head (lanes grouped within half-warps)
#pragma unroll
    for (int off = 1; off <= 8; off <<= 1) ss += __shfl_xor_sync(0xffffffffu, ss, off);
    float sc = rsqrtf(ss + 1e-6f);
    float4 o0 = make_float4(y[0] * sc, y[1] * sc, y[2] * sc, y[3] * sc);
    float4 o1 = make_float4(y[4] * sc, y[5] * sc, y[6] * sc, y[7] * sc);
    *(float4*)&dst[t * HID + c0] = o0;
    *(float4*)&dst[t * HID + c0 + 4] = o1;
}

__global__ void prep_kernel(const float* __restrict__ cwq, const float* __restrict__ cwk) {
    const int t = blockIdx.x;
    const int tid = threadIdx.x;  // 256
    conv_silu_l2(g_Q0, cwq, g_qn, t, tid);
    conv_silu_l2(g_K0, cwk, g_kn, t, tid);
}

// ---------------- state scan: materialize h_kk[t], h_kv[t] ----------------
// grid (16 row-tiles, 16 heads), 256 threads; thread owns (row, 4 cols) of both states.
__global__ void scan_kernel() {
    const int h = blockIdx.y;
    const int i0 = blockIdx.x * 8;
    const int tid = threadIdx.x;
    __shared__ float ds[T_LEN], bs[T_LEN];
    __shared__ __align__(16) float ks[2][DHEAD], vs[2][DHEAD];
    ds[tid] = g_decay[tid * NHEAD + h];
    bs[tid] = g_beta[tid * NHEAD + h];
    if (tid < 32)
        *(float4*)&ks[0][tid * 4] = *(const float4*)&g_kn[h * DHEAD + tid * 4];
    else if (tid < 64) {
        int l = tid - 32;
        *(float4*)&vs[0][l * 4] = *(const float4*)&g_V0[h * DHEAD + l * 4];
    }
    const int row = i0 + (tid >> 5);
    const int j0 = (tid & 31) * 4;
    float kk0 = 0, kk1 = 0, kk2 = 0, kk3 = 0;
    float kv0 = 0, kv1 = 0, kv2 = 0, kv3 = 0;
    for (int t = 0; t < T_LEN; t++) {
        __syncthreads();
        const int cb = t & 1, nb = (t + 1) & 1;
        if (t + 1 < T_LEN) {
            if (tid < 32)
                *(float4*)&ks[nb][tid * 4] =
                    *(const float4*)&g_kn[(t + 1) * HID + h * DHEAD + tid * 4];
            else if (tid < 64) {
                int l = tid - 32;
                *(float4*)&vs[nb][l * 4] =
                    *(const float4*)&g_V0[(t + 1) * HID + h * DHEAD + l * 4];
            }
        }
        const float d = ds[t], b = bs[t];
        const float kr = ks[cb][row];
        float4 kj = *(const float4*)&ks[cb][j0];
        float4 vj = *(const float4*)&vs[cb][j0];
        const float bk = b * kr;
        kk0 = kk0 * d + bk * kj.x; kk1 = kk1 * d + bk * kj.y;
        kk2 = kk2 * d + bk * kj.z; kk3 = kk3 * d + bk * kj.w;
        kv0 = kv0 * d + bk * vj.x; kv1 = kv1 * d + bk * vj.y;
        kv2 = kv2 * d + bk * vj.z; kv3 = kv3 * d + bk * vj.w;
        size_t base = ((size_t)(t * NHEAD + h) * DHEAD + row) * DHEAD + j0;
        *(float4*)&g_hkk[base] = make_float4(kk0, kk1, kk2, kk3);
        *(float4*)&g_hkv[base] = make_float4(kv0, kv1, kv2, kv3);
    }
}

// ---------------- block reduction over 128 threads ----------------
__device__ __forceinline__ float blockReduce128(float v) {
    __shared__ float red[4];
#pragma unroll
    for (int off = 16; off > 0; off >>= 1) v += __shfl_xor_sync(0xffffffffu, v, off);
    const int w = threadIdx.x >> 5;
    if ((threadIdx.x & 31) == 0) red[w] = v;
    __syncthreads();
    v = red[0] + red[1] + red[2] + red[3];
    __syncthreads();
    return v;
}

// ---------------- CG solve + output + rmsnorm, one block per (t,h) ----------------
__global__ void __launch_bounds__(128) solve_kernel(const float* __restrict__ onw) {
    const int h = blockIdx.x;
    const int t = blockIdx.y;
    const int r = threadIdx.x;
    const size_t mbase = (size_t)(t * NHEAD + h) * (DHEAD * DHEAD);
    const float* Arow = g_hkk + mbase + (size_t)r * DHEAD;
    float4 A[32];
#pragma unroll
    for (int i = 0; i < 32; i++) A[i] = *(const float4*)&Arow[i * 4];
    const float lam = g_lamb[h * DHEAD + r];
    const float b = g_qn[t * HID + h * DHEAD + r];

    __shared__ __align__(16) float ps[DHEAD];
    float x = 0.f, rr = b, p = b;
    ps[r] = b;
    float rs = blockReduce128(b * b);  // barrier inside also publishes ps

    for (int it = 0; it < 30; it++) {
        float a0 = 0, a1 = 0, a2 = 0, a3 = 0;
#pragma unroll
        for (int i = 0; i < 32; i++) {
            float4 pv = *(const float4*)&ps[i * 4];
            a0 += A[i].x * pv.x;
            a1 += A[i].y * pv.y;
            a2 += A[i].z * pv.z;
            a3 += A[i].w * pv.w;
        }
        float ap = (a0 + a1) + (a2 + a3) + lam * p;
        float pap = blockReduce128(p * ap);
        float alpha = rs / (pap + 1e-12f);
        x += alpha * p;
        rr -= alpha * ap;
        float rsn = blockReduce128(rr * rr);  // all matvec reads done after this
        float bet = rsn / (rs + 1e-12f);
        p = rr + bet * p;
        rs = rsn;
        ps[r] = p;
        __syncthreads();
    }

    // o[v] = sum_k q_star[k] * h_kv[k][v]
    ps[r] = x;
    __syncthreads();
    float o = 0.f;
    const float* kvp = g_hkv + mbase + r;
#pragma unroll 8
    for (int k2 = 0; k2 < DHEAD; k2++) o += ps[k2] * kvp[(size_t)k2 * DHEAD];

    float ms = blockReduce128(o * o) * (1.0f / 128.0f);
    float sc = rsqrtf(ms + 1e-5f);
    g_on[t * HID + h * DHEAD + r] = o * sc * onw[r];
}

// ---------------- launch ----------------
extern "C" void kernel_launch(void* const* d_in, const int* in_sizes, int n_in,
                              void* d_out, int out_size) {
    const float* x    = (const float*)d_in[0];
    const float* Wq   = (const float*)d_in[1];
    const float* Wk   = (const float*)d_in[2];
    const float* Wv   = (const float*)d_in[3];
    const float* Wa   = (const float*)d_in[4];
    const float* ba   = (const float*)d_in[5];
    const float* Wb   = (const float*)d_in[6];
    const float* bb   = (const float*)d_in[7];
    const float* cwq  = (const float*)d_in[8];
    const float* cwk  = (const float*)d_in[9];
    const float* lp   = (const float*)d_in[10];
    const float* onw  = (const float*)d_in[11];
    const float* Wo   = (const float*)d_in[12];
    float* out = (float*)d_out;

    float *Q0p, *K0p, *V0p, *onp;
    cudaGetSymbolAddress((void**)&Q0p, g_Q0);
    cudaGetSymbolAddress((void**)&K0p, g_K0);
    cudaGetSymbolAddress((void**)&V0p, g_V0);
    cudaGetSymbolAddress((void**)&onp, g_on);

    dim3 ggrid(KD / 64, T_LEN / 64);
    gemm_kernel<<<ggrid, 256>>>(x, Wq, Q0p, KD);
    gemm_kernel<<<ggrid, 256>>>(x, Wk, K0p, KD);
    gemm_kernel<<<ggrid, 256>>>(x, Wv, V0p, KD);

    bg_kernel<<<T_LEN, 128>>>(x, Wa, ba, Wb, bb);
    lamb_kernel<<<KD / 256, 256>>>(lp);
    prep_kernel<<<T_LEN, 256>>>(cwq, cwk);
    scan_kernel<<<dim3(16, NHEAD), 256>>>();
    solve_kernel<<<dim3(NHEAD, T_LEN), 128>>>(onw);

    gemm_kernel<<<dim3(HID / 64, T_LEN / 64), 256>>>(onp, Wo, out, HID);
}

// round 2
// speedup vs baseline: 1.3334x; 1.3334x over previous
#include <cuda_runtime.h>
#include <math.h>

#define T_LEN 256
#define HID   2048
#define NHEAD 16
#define DHEAD 128
#define KD    2048

// ---------------- scratch ----------------
__device__ float g_Q0[T_LEN * KD];
__device__ float g_K0[T_LEN * KD];
__device__ float g_V0[T_LEN * KD];
__device__ float g_qn[T_LEN * KD];
__device__ float g_kn[T_LEN * KD];
__device__ float g_beta[T_LEN * NHEAD];
__device__ float g_decay[T_LEN * NHEAD];
__device__ float g_lamb[KD];
__device__ float g_on[T_LEN * KD];
__device__ float g_hkk[(size_t)T_LEN * NHEAD * DHEAD * DHEAD];  // 256 MB
__device__ float g_hkv[(size_t)T_LEN * NHEAD * DHEAD * DHEAD];  // 256 MB

// ---------------- f32x2 helpers (Blackwell FFMA2) ----------------
typedef unsigned long long u64;
__device__ __forceinline__ u64 splat2(float a) {
    u64 d; unsigned u = __float_as_uint(a);
    asm("mov.b64 %0, {%1, %1};" : "=l"(d) : "r"(u));
    return d;
}
__device__ __forceinline__ void ffma2(u64& d, u64 a, u64 b) {
    asm("fma.rn.f32x2 %0, %1, %2, %0;" : "+l"(d) : "l"(a), "l"(b));
}
__device__ __forceinline__ float2 unpk(u64 v) {
    unsigned lo, hi;
    asm("mov.b64 {%0, %1}, %2;" : "=r"(lo), "=r"(hi) : "l"(v));
    return make_float2(__uint_as_float(lo), __uint_as_float(hi));
}

// ---------------- GEMM tile core: C[m0:+64, n0:+64] += X[.,2048] @ W[2048,N] ----------------
// 256 threads, BK=32, 4x4 micro-tile via FFMA2.
__device__ __forceinline__ void gemm_tile(const float* __restrict__ X,
                                          const float* __restrict__ W,
                                          float* __restrict__ C, int N,
                                          int m0, int n0) {
    __shared__ __align__(16) float As[64][36];   // [m][k], padded
    __shared__ __align__(16) float Bs[32][64];   // [k][n]
    const int tid = threadIdx.x;
    const int tn4 = (tid & 15) * 4;
    const int tm4 = (tid >> 4) * 4;
    const int lrow = tid >> 2;           // 0..63
    const int lk   = (tid & 3) * 8;      // 0,8,16,24
    const int bkk  = tid >> 3;           // 0..31
    const int bn8  = (tid & 7) * 8;      // 0..56

    u64 acc[4][2];
#pragma unroll
    for (int i = 0; i < 4; i++) { acc[i][0] = 0ull; acc[i][1] = 0ull; }

    for (int k0 = 0; k0 < HID; k0 += 32) {
        float4 xa = *(const float4*)&X[(m0 + lrow) * HID + k0 + lk];
        float4 xb = *(const float4*)&X[(m0 + lrow) * HID + k0 + lk + 4];
        *(float4*)&As[lrow][lk]     = xa;
        *(float4*)&As[lrow][lk + 4] = xb;
        float4 wa = *(const float4*)&W[(k0 + bkk) * N + n0 + bn8];
        float4 wb = *(const float4*)&W[(k0 + bkk) * N + n0 + bn8 + 4];
        *(float4*)&Bs[bkk][bn8]     = wa;
        *(float4*)&Bs[bkk][bn8 + 4] = wb;
        __syncthreads();
#pragma unroll
        for (int kk = 0; kk < 32; kk++) {
            ulonglong2 bv = *(const ulonglong2*)&Bs[kk][tn4];
            u64 s0 = splat2(As[tm4 + 0][kk]);
            u64 s1 = splat2(As[tm4 + 1][kk]);
            u64 s2 = splat2(As[tm4 + 2][kk]);
            u64 s3 = splat2(As[tm4 + 3][kk]);
            ffma2(acc[0][0], s0, bv.x); ffma2(acc[0][1], s0, bv.y);
            ffma2(acc[1][0], s1, bv.x); ffma2(acc[1][1], s1, bv.y);
            ffma2(acc[2][0], s2, bv.x); ffma2(acc[2][1], s2, bv.y);
            ffma2(acc[3][0], s3, bv.x); ffma2(acc[3][1], s3, bv.y);
        }
        __syncthreads();
    }
#pragma unroll
    for (int i = 0; i < 4; i++) {
        float2 lo = unpk(acc[i][0]);
        float2 hi = unpk(acc[i][1]);
        *(float4*)&C[(m0 + tm4 + i) * N + n0 + tn4] = make_float4(lo.x, lo.y, hi.x, hi.y);
    }
}

// fused Q/K/V: grid (96, 4); mat = bx%3 so same-n0 blocks are adjacent (L2 reuse of X)
__global__ void __launch_bounds__(256) qkv_kernel(const float* __restrict__ x,
                                                  const float* __restrict__ Wq,
                                                  const float* __restrict__ Wk,
                                                  const float* __restrict__ Wv) {
    const int gx = blockIdx.x;
    const int mat = gx % 3;
    const int n0 = (gx / 3) * 64;
    const int m0 = blockIdx.y * 64;
    const float* W = (mat == 0) ? Wq : (mat == 1) ? Wk : Wv;
    float* C = (mat == 0) ? g_Q0 : (mat == 1) ? g_K0 : g_V0;
    gemm_tile(x, W, C, KD, m0, n0);
}

__global__ void __launch_bounds__(256) out_kernel(const float* __restrict__ Wo,
                                                  float* __restrict__ out) {
    gemm_tile(g_on, Wo, out, HID, blockIdx.y * 64, blockIdx.x * 64);
}

// ---------------- beta / decay mini-GEMM: [256,2048] @ [2048,32] ----------------
// grid 16 (m-tiles of 16), 256 threads = 32 cols x 8 row-pairs
__global__ void __launch_bounds__(256) bg_kernel(const float* __restrict__ x,
                                                 const float* __restrict__ Wa,
                                                 const float* __restrict__ ba,
                                                 const float* __restrict__ Wb,
                                                 const float* __restrict__ bb) {
    __shared__ float Xs[32][17];   // [k][m]
    __shared__ float Ws[32][32];   // [k][n]
    const int tid = threadIdx.x;
    const int m0 = blockIdx.x * 16;
    const int n = tid & 31;
    const int mg = tid >> 5;        // 0..7 -> rows mg*2, mg*2+1
    const int lxm = tid >> 4;       // 0..15
    const int lxk = (tid & 15) * 2; // 0..30

    float acc0 = 0.f, acc1 = 0.f;
    for (int k0 = 0; k0 < HID; k0 += 32) {
        float2 xv = *(const float2*)&x[(m0 + lxm) * HID + k0 + lxk];
        Xs[lxk][lxm] = xv.x;
        Xs[lxk + 1][lxm] = xv.y;
        const int i4 = tid * 4;
        const int wk = i4 >> 5, wn = i4 & 31;
#pragma unroll
        for (int j = 0; j < 4; j++) {
            int nn = wn + j;
            Ws[wk][nn] = (nn < 16) ? Wa[(k0 + wk) * NHEAD + nn]
                                   : Wb[(k0 + wk) * NHEAD + nn - 16];
        }
        __syncthreads();
#pragma unroll
        for (int kk = 0; kk < 32; kk++) {
            float w = Ws[kk][n];
            acc0 += Xs[kk][mg * 2] * w;
            acc1 += Xs[kk][mg * 2 + 1] * w;
        }
        __syncthreads();
    }
    const int row0 = m0 + mg * 2;
    if (n < 16) {
        float z0 = acc0 + ba[n], z1 = acc1 + ba[n];
        g_decay[row0 * NHEAD + n] = 1.f / (1.f + expf(-z0));
        g_decay[(row0 + 1) * NHEAD + n] = 1.f / (1.f + expf(-z1));
    } else {
        int c = n - 16;
        float z0 = acc0 + bb[c], z1 = acc1 + bb[c];
        g_beta[row0 * NHEAD + c] = 1.f / (1.f + expf(-z0));
        g_beta[(row0 + 1) * NHEAD + c] = 1.f / (1.f + expf(-z1));
    }
}

// ---------------- lambda = softplus(lp) + 0.25 ----------------
__global__ void lamb_kernel(const float* __restrict__ lp) {
    int i = blockIdx.x * 256 + threadIdx.x;
    if (i < KD) {
        float v = lp[i];
        float sp = (v > 20.f) ? v : log1pf(expf(v));
        g_lamb[i] = sp + 0.25f;
    }
}

// ---------------- conv(4)+silu+l2norm ----------------
__device__ __forceinline__ void conv_silu_l2(const float* __restrict__ src,
                                             const float* __restrict__ cw,
                                             float* __restrict__ dst,
                                             int t, int tid) {
    const int c0 = tid * 8;
    float wv[8][4];
#pragma unroll
    for (int e = 0; e < 8; e++) {
        float4 f = *(const float4*)&cw[(c0 + e) * 4];
        wv[e][0] = f.x; wv[e][1] = f.y; wv[e][2] = f.z; wv[e][3] = f.w;
    }
    float y[8];
#pragma unroll
    for (int e = 0; e < 8; e++) y[e] = 0.f;
#pragma unroll
    for (int i = 0; i < 4; i++) {
        int ts = t + i - 3;
        if (ts >= 0) {
            float4 xa = *(const float4*)&src[ts * HID + c0];
            float4 xb = *(const float4*)&src[ts * HID + c0 + 4];
            float xv[8] = {xa.x, xa.y, xa.z, xa.w, xb.x, xb.y, xb.z, xb.w};
#pragma unroll
            for (int e = 0; e < 8; e++) y[e] += xv[e] * wv[e][i];
        }
    }
#pragma unroll
    for (int e = 0; e < 8; e++) {
        float s = 1.f / (1.f + expf(-y[e]));
        y[e] *= s;
    }
    float ss = 0.f;
#pragma unroll
    for (int e = 0; e < 8; e++) ss += y[e] * y[e];
#pragma unroll
    for (int off = 1; off <= 8; off <<= 1) ss += __shfl_xor_sync(0xffffffffu, ss, off);
    float sc = rsqrtf(ss + 1e-6f);
    float4 o0 = make_float4(y[0] * sc, y[1] * sc, y[2] * sc, y[3] * sc);
    float4 o1 = make_float4(y[4] * sc, y[5] * sc, y[6] * sc, y[7] * sc);
    *(float4*)&dst[t * HID + c0] = o0;
    *(float4*)&dst[t * HID + c0 + 4] = o1;
}

__global__ void prep_kernel(const float* __restrict__ cwq, const float* __restrict__ cwk) {
    const int t = blockIdx.x;
    const int tid = threadIdx.x;  // 256
    conv_silu_l2(g_Q0, cwq, g_qn, t, tid);
    conv_silu_l2(g_K0, cwk, g_kn, t, tid);
}

// ---------------- state scan ----------------
__global__ void scan_kernel() {
    const int h = blockIdx.y;
    const int i0 = blockIdx.x * 8;
    const int tid = threadIdx.x;
    __shared__ float ds[T_LEN], bs[T_LEN];
    __shared__ __align__(16) float ks[2][DHEAD], vs[2][DHEAD];
    ds[tid] = g_decay[tid * NHEAD + h];
    bs[tid] = g_beta[tid * NHEAD + h];
    if (tid < 32)
        *(float4*)&ks[0][tid * 4] = *(const float4*)&g_kn[h * DHEAD + tid * 4];
    else if (tid < 64) {
        int l = tid - 32;
        *(float4*)&vs[0][l * 4] = *(const float4*)&g_V0[h * DHEAD + l * 4];
    }
    const int row = i0 + (tid >> 5);
    const int j0 = (tid & 31) * 4;
    float kk0 = 0, kk1 = 0, kk2 = 0, kk3 = 0;
    float kv0 = 0, kv1 = 0, kv2 = 0, kv3 = 0;
    for (int t = 0; t < T_LEN; t++) {
        __syncthreads();
        const int cb = t & 1, nb = (t + 1) & 1;
        if (t + 1 < T_LEN) {
            if (tid < 32)
                *(float4*)&ks[nb][tid * 4] =
                    *(const float4*)&g_kn[(t + 1) * HID + h * DHEAD + tid * 4];
            else if (tid < 64) {
                int l = tid - 32;
                *(float4*)&vs[nb][l * 4] =
                    *(const float4*)&g_V0[(t + 1) * HID + h * DHEAD + l * 4];
            }
        }
        const float d = ds[t], b = bs[t];
        const float kr = ks[cb][row];
        float4 kj = *(const float4*)&ks[cb][j0];
        float4 vj = *(const float4*)&vs[cb][j0];
        const float bk = b * kr;
        kk0 = kk0 * d + bk * kj.x; kk1 = kk1 * d + bk * kj.y;
        kk2 = kk2 * d + bk * kj.z; kk3 = kk3 * d + bk * kj.w;
        kv0 = kv0 * d + bk * vj.x; kv1 = kv1 * d + bk * vj.y;
        kv2 = kv2 * d + bk * vj.z; kv3 = kv3 * d + bk * vj.w;
        size_t base = ((size_t)(t * NHEAD + h) * DHEAD + row) * DHEAD + j0;
        *(float4*)&g_hkk[base] = make_float4(kk0, kk1, kk2, kk3);
        *(float4*)&g_hkv[base] = make_float4(kv0, kv1, kv2, kv3);
    }
}

// ---------------- block reduce (parity-buffered: 1 sync per call) ----------------
__device__ __forceinline__ float blockReduce128(float v, int pb) {
    __shared__ float red[2][4];
#pragma unroll
    for (int off = 16; off > 0; off >>= 1) v += __shfl_xor_sync(0xffffffffu, v, off);
    const int w = threadIdx.x >> 5;
    if ((threadIdx.x & 31) == 0) red[pb][w] = v;
    __syncthreads();
    return red[pb][0] + red[pb][1] + red[pb][2] + red[pb][3];
}

// ---------------- CG solve + output + rmsnorm ----------------
__global__ void __launch_bounds__(128) solve_kernel(const float* __restrict__ onw) {
    const int h = blockIdx.x;
    const int t = blockIdx.y;
    const int r = threadIdx.x;
    const size_t mbase = (size_t)(t * NHEAD + h) * (DHEAD * DHEAD);
    const float* Arow = g_hkk + mbase + (size_t)r * DHEAD;
    ulonglong2 A2[32];
#pragma unroll
    for (int i = 0; i < 32; i++) A2[i] = *(const ulonglong2*)&Arow[i * 4];
    const float lam = g_lamb[h * DHEAD + r];
    const float b = g_qn[t * HID + h * DHEAD + r];

    __shared__ __align__(16) float ps[DHEAD];
    float xx = 0.f, rr = b, p = b;
    ps[r] = b;
    int par = 0;
    float rs = blockReduce128(b * b, par); par ^= 1;   // sync publishes ps

    for (int it = 0; it < 30; it++) {
        u64 aA = 0ull, aB = 0ull, aC = 0ull, aD = 0ull;
#pragma unroll
        for (int i = 0; i < 32; i += 2) {
            ulonglong2 p0 = *(const ulonglong2*)&ps[i * 4];
            ulonglong2 p1 = *(const ulonglong2*)&ps[i * 4 + 4];
            ffma2(aA, A2[i].x, p0.x);     ffma2(aB, A2[i].y, p0.y);
            ffma2(aC, A2[i + 1].x, p1.x); ffma2(aD, A2[i + 1].y, p1.y);
        }
        float2 fa = unpk(aA), fb = unpk(aB), fc = unpk(aC), fd = unpk(aD);
        float ap = ((fa.x + fa.y) + (fb.x + fb.y)) + ((fc.x + fc.y) + (fd.x + fd.y)) + lam * p;
        float pap = blockReduce128(p * ap, par); par ^= 1;   // sync also fences ps reads
        float alpha = rs / (pap + 1e-12f);
        xx += alpha * p;
        rr -= alpha * ap;
        float rsn = blockReduce128(rr * rr, par); par ^= 1;
        float bet = rsn / (rs + 1e-12f);
        p = rr + bet * p;
        rs = rsn;
        ps[r] = p;
        __syncthreads();
    }

    ps[r] = xx;
    __syncthreads();
    const float* kvp = g_hkv + mbase + r;
    float o0 = 0, o1 = 0, o2 = 0, o3 = 0;
#pragma unroll
    for (int k2 = 0; k2 < DHEAD; k2 += 4) {
        o0 += ps[k2]     * kvp[(size_t)k2 * DHEAD];
        o1 += ps[k2 + 1] * kvp[(size_t)(k2 + 1) * DHEAD];
        o2 += ps[k2 + 2] * kvp[(size_t)(k2 + 2) * DHEAD];
        o3 += ps[k2 + 3] * kvp[(size_t)(k2 + 3) * DHEAD];
    }
    float o = (o0 + o1) + (o2 + o3);
    float ms = blockReduce128(o * o, par) * (1.0f / 128.0f);
    float sc = rsqrtf(ms + 1e-5f);
    g_on[t * HID + h * DHEAD + r] = o * sc * onw[r];
}

// ---------------- launch ----------------
extern "C" void kernel_launch(void* const* d_in, const int* in_sizes, int n_in,
                              void* d_out, int out_size) {
    const float* x    = (const float*)d_in[0];
    const float* Wq   = (const float*)d_in[1];
    const float* Wk   = (const float*)d_in[2];
    const float* Wv   = (const float*)d_in[3];
    const float* Wa   = (const float*)d_in[4];
    const float* ba   = (const float*)d_in[5];
    const float* Wb   = (const float*)d_in[6];
    const float* bb   = (const float*)d_in[7];
    const float* cwq  = (const float*)d_in[8];
    const float* cwk  = (const float*)d_in[9];
    const float* lp   = (const float*)d_in[10];
    const float* onw  = (const float*)d_in[11];
    const float* Wo   = (const float*)d_in[12];
    float* out = (float*)d_out;

    qkv_kernel<<<dim3(96, 4), 256>>>(x, Wq, Wk, Wv);
    bg_kernel<<<16, 256>>>(x, Wa, ba, Wb, bb);
    lamb_kernel<<<KD / 256, 256>>>(lp);
    prep_kernel<<<T_LEN, 256>>>(cwq, cwk);
    scan_kernel<<<dim3(16, NHEAD), 256>>>();
    solve_kernel<<<dim3(NHEAD, T_LEN), 128>>>(onw);
    out_kernel<<<dim3(HID / 64, T_LEN / 64), 256>>>(Wo, out);
}